// round 11
// baseline (speedup 1.0000x reference)
#include <cuda_runtime.h>
#include <cuda_fp16.h>
#include <math.h>
#include <stdint.h>

// Problem constants: B=4, T=2048, C=1024, H=16, D=64
#define QKV_ELEMS (4 * 16 * 2048 * 64)

__device__ float g_q[QKV_ELEMS];
__device__ float g_k[QKV_ELEMS];
__device__ float g_v[QKV_ELEMS];
__device__ float g_ctx[QKV_ELEMS];

__device__ __forceinline__ uint32_t pack2h(float a, float b) {
    half2 h = __floats2half2_rn(a, b);   // low = a, high = b
    return *reinterpret_cast<uint32_t*>(&h);
}

__device__ __forceinline__ void mma_f16(float c[4],
                                        uint32_t a0, uint32_t a1, uint32_t a2, uint32_t a3,
                                        uint32_t b0, uint32_t b1) {
    asm volatile(
        "mma.sync.aligned.m16n8k16.row.col.f32.f16.f16.f32 "
        "{%0,%1,%2,%3}, {%4,%5,%6,%7}, {%8,%9}, {%0,%1,%2,%3};"
        : "+f"(c[0]), "+f"(c[1]), "+f"(c[2]), "+f"(c[3])
        : "r"(a0), "r"(a1), "r"(a2), "r"(a3), "r"(b0), "r"(b1));
}

// ---------------------------------------------------------------------------
// fp16 tensor-core GEMM: C[M,N] = A[M,K=1024] @ W[1024,N]
// Block tile 128x128, Kchunk 32, 8 warps (2x4), warp tile 64x32.
// Operands packed half2 along k, row stride 20 words (16 payload + 4 pad):
//   - fragment LDS bank = (20g + t) mod 32 -> 32 distinct (conflict-free)
//   - staging STS.128 per-phase word groups 20*l mod 32 -> distinct
// SRC_CTX=1: A = g_ctx. EPI=0: scatter q/k/v. EPI=1: row-major out.
// ---------------------------------------------------------------------------
template <int N, int EPI, int SRC_CTX>
__global__ void __launch_bounds__(256) mma_gemm(const float* __restrict__ Ain,
                                                const float* __restrict__ W,
                                                float* __restrict__ out)
{
    const int K = 1024;
    const int LDH = 20;             // padded row stride (half2 words)
    const int BUF = 128 * LDH;      // 2560 words per operand buffer
    extern __shared__ uint32_t sh[];
    uint32_t* As = sh;              // 2 * BUF
    uint32_t* Bs = sh + 2 * BUF;    // 2 * BUF

    const float* A = SRC_CTX ? (const float*)g_ctx : Ain;

    int tid = threadIdx.x;
    int lane = tid & 31;
    int wid = tid >> 5;
    int wm = wid & 1;               // 64-row slab
    int wn = wid >> 1;              // 32-col slab
    int brow = blockIdx.y * 128;
    int bcol = blockIdx.x * 128;

    float c[4][4][4];
#pragma unroll
    for (int mt = 0; mt < 4; mt++)
#pragma unroll
        for (int nt = 0; nt < 4; nt++)
#pragma unroll
            for (int e = 0; e < 4; e++) c[mt][nt][e] = 0.f;

    // staging: row = tid&127, k-sub-half s = tid>>7 (16 k-values each)
    int srow = tid & 127;
    int ss   = tid >> 7;

    const float* Ap = A + (size_t)(brow + srow) * K + ss * 16;
    const float* Wp = W + bcol + srow;

    float4 ar[4];
    float bv[16];

#define LDG_TILE(kt)                                                         \
    {                                                                        \
        int k0 = (kt) * 32;                                                  \
        _Pragma("unroll")                                                    \
        for (int i = 0; i < 4; i++)                                          \
            ar[i] = *(const float4*)(Ap + k0 + i * 4);                       \
        _Pragma("unroll")                                                    \
        for (int j = 0; j < 16; j++)                                         \
            bv[j] = Wp[(size_t)(k0 + ss * 16 + j) * N];                      \
    }

#define STS_TILE(p)                                                          \
    {                                                                        \
        uint32_t* as = As + (p) * BUF + srow * LDH + ss * 8;                 \
        uint32_t* bs = Bs + (p) * BUF + srow * LDH + ss * 8;                 \
        uint32_t w[8];                                                       \
        _Pragma("unroll")                                                    \
        for (int i = 0; i < 4; i++) {                                        \
            w[2 * i + 0] = pack2h(ar[i].x, ar[i].y);                         \
            w[2 * i + 1] = pack2h(ar[i].z, ar[i].w);                         \
        }                                                                    \
        *(uint4*)&as[0] = *(uint4*)&w[0];                                    \
        *(uint4*)&as[4] = *(uint4*)&w[4];                                    \
        _Pragma("unroll")                                                    \
        for (int j = 0; j < 8; j++)                                          \
            w[j] = pack2h(bv[2 * j], bv[2 * j + 1]);                         \
        *(uint4*)&bs[0] = *(uint4*)&w[0];                                    \
        *(uint4*)&bs[4] = *(uint4*)&w[4];                                    \
    }

    LDG_TILE(0);
    STS_TILE(0);
    __syncthreads();

    int mrow = wm * 64 + (lane >> 2);
    int ncol = wn * 32 + (lane >> 2);
    int tk = lane & 3;

    for (int kt = 0; kt < 32; kt++) {
        int p = kt & 1;
        if (kt + 1 < 32) LDG_TILE(kt + 1);

        const uint32_t* asp = As + p * BUF;
        const uint32_t* bsp = Bs + p * BUF;
#pragma unroll
        for (int ks = 0; ks < 2; ks++) {
            int k0 = ks * 8 + tk;
            uint32_t a[4][4], b[4][2];
#pragma unroll
            for (int mt = 0; mt < 4; mt++) {
                int r = mrow + mt * 16;
                a[mt][0] = asp[r * LDH + k0];
                a[mt][1] = asp[(r + 8) * LDH + k0];
                a[mt][2] = asp[r * LDH + k0 + 4];
                a[mt][3] = asp[(r + 8) * LDH + k0 + 4];
            }
#pragma unroll
            for (int nt = 0; nt < 4; nt++) {
                int n = ncol + nt * 8;
                b[nt][0] = bsp[n * LDH + k0];
                b[nt][1] = bsp[n * LDH + k0 + 4];
            }
#pragma unroll
            for (int mt = 0; mt < 4; mt++)
#pragma unroll
                for (int nt = 0; nt < 4; nt++)
                    mma_f16(c[mt][nt], a[mt][0], a[mt][1], a[mt][2], a[mt][3],
                            b[nt][0], b[nt][1]);
        }

        if (kt + 1 < 32) STS_TILE((kt + 1) & 1);
        __syncthreads();
    }
#undef LDG_TILE
#undef STS_TILE

    // epilogue (fragment layout identical to R9/R10)
    int row0 = brow + wm * 64 + (lane >> 2);
    int col0 = bcol + wn * 32 + (lane & 3) * 2;

    if (EPI == 0) {
        int which = bcol >> 10;
        float* dst = (which == 0) ? g_q : ((which == 1) ? g_k : g_v);
#pragma unroll
        for (int mt = 0; mt < 4; mt++) {
#pragma unroll
            for (int nt = 0; nt < 4; nt++) {
                int col = col0 + nt * 8;
                int cc = col & 1023;
                int h = cc >> 6, d = cc & 63;
#pragma unroll
                for (int half = 0; half < 2; half++) {
                    int r = row0 + mt * 16 + half * 8;
                    int bb = r >> 11, t = r & 2047;
                    float2 v;
                    v.x = c[mt][nt][half * 2 + 0];
                    v.y = c[mt][nt][half * 2 + 1];
                    *(float2*)&dst[((((size_t)bb * 16 + h) * 2048 + t) << 6) + d] = v;
                }
            }
        }
    } else {
#pragma unroll
        for (int mt = 0; mt < 4; mt++) {
#pragma unroll
            for (int nt = 0; nt < 4; nt++) {
                int col = col0 + nt * 8;
#pragma unroll
                for (int half = 0; half < 2; half++) {
                    int r = row0 + mt * 16 + half * 8;
                    float2 v;
                    v.x = c[mt][nt][half * 2 + 0];
                    v.y = c[mt][nt][half * 2 + 1];
                    *(float2*)&out[(size_t)r * N + col] = v;
                }
            }
        }
    }
}

// ---------------------------------------------------------------------------
// Causal flash attention, fp16 tensor cores (unchanged from R10 — passing).
// ---------------------------------------------------------------------------
__global__ void __launch_bounds__(256) attn_h_kernel()
{
    extern __shared__ uint32_t sm[];
    const int LDH = 36;
    uint32_t* Qh = sm;
    uint32_t* Kh = sm + 2304;
    uint32_t* Vt = sm + 4608;
    uint32_t* Ph = sm + 6912;
    float*    Ss = (float*)(sm + 9216);
    float* sm_m    = (float*)(sm + 13568);
    float* sm_l    = sm_m + 64;
    float* sm_corr = sm_m + 128;

    int bh = blockIdx.y;
    int qt = gridDim.x - 1 - blockIdx.x;
    int h = bh & 15, bb = bh >> 4;

    const float* Qp = g_q + ((size_t)bh * 2048 + qt * 64) * 64;
    const float* Kp = g_k + (size_t)bh * 2048 * 64;
    const float* Vp = g_v + (size_t)bh * 2048 * 64;

    int tid = threadIdx.x;
    int lane = tid & 31;
    int wid = tid >> 5;
    int wm = wid & 3;
    int wn = wid >> 2;
    int g = lane >> 2;
    int t = lane & 3;

    int r4 = tid >> 2;
    int c4 = tid & 3;

    {
        const float* qr = Qp + r4 * 64 + c4 * 16;
        uint32_t w[8];
#pragma unroll
        for (int f = 0; f < 4; f++) {
            float4 v = *(const float4*)(qr + f * 4);
            w[2 * f + 0] = pack2h(v.x, v.y);
            w[2 * f + 1] = pack2h(v.z, v.w);
        }
        *(uint4*)&Qh[r4 * LDH + c4 * 8]     = *(uint4*)&w[0];
        *(uint4*)&Qh[r4 * LDH + c4 * 8 + 4] = *(uint4*)&w[4];
    }
    if (tid < 64) {
        sm_m[tid] = -1e30f;
        sm_l[tid] = 0.f;
    }

    float o[4][4];
#pragma unroll
    for (int nt = 0; nt < 4; nt++)
#pragma unroll
        for (int e = 0; e < 4; e++) o[nt][e] = 0.f;

    const float scale = 0.125f;
    int arow = 16 * wm + g;

    int v_kp = 4 * wid + (lane & 3);
    int v_d0 = lane >> 2;

    for (int kt = 0; kt <= qt; kt++) {
        __syncthreads();
        {
            const float* kr = Kp + (size_t)(kt * 64 + r4) * 64 + c4 * 16;
            uint32_t w[8];
#pragma unroll
            for (int f = 0; f < 4; f++) {
                float4 v = *(const float4*)(kr + f * 4);
                w[2 * f + 0] = pack2h(v.x, v.y);
                w[2 * f + 1] = pack2h(v.z, v.w);
            }
            *(uint4*)&Kh[r4 * LDH + c4 * 8]     = *(uint4*)&w[0];
            *(uint4*)&Kh[r4 * LDH + c4 * 8 + 4] = *(uint4*)&w[4];
        }
        {
            const float* v0p = Vp + (size_t)(kt * 64 + 2 * v_kp) * 64;
            const float* v1p = v0p + 64;
#pragma unroll
            for (int j = 0; j < 8; j++) {
                int d = v_d0 + 8 * j;
                Vt[d * LDH + v_kp] = pack2h(v0p[d], v1p[d]);
            }
        }
        __syncthreads();

        float cs[4][4];
#pragma unroll
        for (int nt = 0; nt < 4; nt++)
#pragma unroll
            for (int e = 0; e < 4; e++) cs[nt][e] = 0.f;

#pragma unroll
        for (int ks = 0; ks < 4; ks++) {
            int k0 = ks * 8 + t;
            uint32_t a0 = Qh[arow * LDH + k0];
            uint32_t a1 = Qh[(arow + 8) * LDH + k0];
            uint32_t a2 = Qh[arow * LDH + k0 + 4];
            uint32_t a3 = Qh[(arow + 8) * LDH + k0 + 4];
#pragma unroll
            for (int nt = 0; nt < 4; nt++) {
                int n = 32 * wn + nt * 8 + g;
                uint32_t b0 = Kh[n * LDH + k0];
                uint32_t b1 = Kh[n * LDH + k0 + 4];
                mma_f16(cs[nt], a0, a1, a2, a3, b0, b1);
            }
        }

#pragma unroll
        for (int nt = 0; nt < 4; nt++) {
            int col = 32 * wn + nt * 8 + 2 * t;
            *(float2*)&Ss[arow * 68 + col] =
                make_float2(cs[nt][0] * scale, cs[nt][1] * scale);
            *(float2*)&Ss[(arow + 8) * 68 + col] =
                make_float2(cs[nt][2] * scale, cs[nt][3] * scale);
        }
        __syncthreads();

        {
            int r = r4;
            int c0 = c4 * 16;
            float* row = &Ss[r * 68];
            bool diag = (kt == qt);
            float v[16];
#pragma unroll
            for (int f = 0; f < 4; f++) {
                float4 x = *(float4*)&row[c0 + f * 4];
                v[f * 4 + 0] = x.x; v[f * 4 + 1] = x.y;
                v[f * 4 + 2] = x.z; v[f * 4 + 3] = x.w;
            }
            if (diag) {
#pragma unroll
                for (int j = 0; j < 16; j++)
                    if (c0 + j > r) v[j] = -1e30f;
            }
            float mx = v[0];
#pragma unroll
            for (int j = 1; j < 16; j++) mx = fmaxf(mx, v[j]);
            mx = fmaxf(mx, __shfl_xor_sync(0xffffffffu, mx, 1));
            mx = fmaxf(mx, __shfl_xor_sync(0xffffffffu, mx, 2));
            float mprev = sm_m[r];
            float nm = fmaxf(mprev, mx);
            float sum = 0.f;
#pragma unroll
            for (int j = 0; j < 16; j++) {
                v[j] = __expf(v[j] - nm);
                sum += v[j];
            }
            uint32_t pw[8];
#pragma unroll
            for (int j = 0; j < 8; j++)
                pw[j] = pack2h(v[2 * j], v[2 * j + 1]);
            *(uint4*)&Ph[r * LDH + c4 * 8]     = *(uint4*)&pw[0];
            *(uint4*)&Ph[r * LDH + c4 * 8 + 4] = *(uint4*)&pw[4];
            sum += __shfl_xor_sync(0xffffffffu, sum, 1);
            sum += __shfl_xor_sync(0xffffffffu, sum, 2);
            if (c4 == 0) {
                float corr = __expf(mprev - nm);
                sm_l[r] = sm_l[r] * corr + sum;
                sm_m[r] = nm;
                sm_corr[r] = corr;
            }
        }
        __syncthreads();

        {
            float cr0 = sm_corr[arow];
            float cr1 = sm_corr[arow + 8];
#pragma unroll
            for (int nt = 0; nt < 4; nt++) {
                o[nt][0] *= cr0; o[nt][1] *= cr0;
                o[nt][2] *= cr1; o[nt][3] *= cr1;
            }
#pragma unroll
            for (int ks = 0; ks < 4; ks++) {
                int k0 = ks * 8 + t;
                uint32_t a0 = Ph[arow * LDH + k0];
                uint32_t a1 = Ph[(arow + 8) * LDH + k0];
                uint32_t a2 = Ph[arow * LDH + k0 + 4];
                uint32_t a3 = Ph[(arow + 8) * LDH + k0 + 4];
#pragma unroll
                for (int nt = 0; nt < 4; nt++) {
                    int n = 32 * wn + nt * 8 + g;
                    uint32_t b0 = Vt[n * LDH + k0];
                    uint32_t b1 = Vt[n * LDH + k0 + 4];
                    mma_f16(o[nt], a0, a1, a2, a3, b0, b1);
                }
            }
        }
    }

    {
        float il0 = 1.f / sm_l[arow];
        float il1 = 1.f / sm_l[arow + 8];
        int q0 = qt * 64 + arow;
#pragma unroll
        for (int nt = 0; nt < 4; nt++) {
            int dcol = 32 * wn + nt * 8 + 2 * t;
            *(float2*)&g_ctx[((size_t)bb * 2048 + q0) * 1024 + h * 64 + dcol] =
                make_float2(o[nt][0] * il0, o[nt][1] * il0);
            *(float2*)&g_ctx[((size_t)bb * 2048 + q0 + 8) * 1024 + h * 64 + dcol] =
                make_float2(o[nt][2] * il1, o[nt][3] * il1);
        }
    }
}

// ---------------------------------------------------------------------------
extern "C" void kernel_launch(void* const* d_in, const int* in_sizes, int n_in,
                              void* d_out, int out_size)
{
    const float* x     = (const float*)d_in[0];  // [4,2048,1024]
    const float* w_qkv = (const float*)d_in[1];  // [1024,3072]
    const float* w_out = (const float*)d_in[2];  // [1024,1024]
    float* out = (float*)d_out;                  // [4,2048,1024]

    (void)in_sizes; (void)n_in; (void)out_size;

    const int gemm_smem = 4 * 128 * 20 * (int)sizeof(uint32_t);  // 40960
    const int attn_smem = 13760 * (int)sizeof(uint32_t);         // 55040

    cudaFuncSetAttribute(mma_gemm<3072, 0, 0>,
                         cudaFuncAttributeMaxDynamicSharedMemorySize, gemm_smem);
    cudaFuncSetAttribute(mma_gemm<1024, 1, 1>,
                         cudaFuncAttributeMaxDynamicSharedMemorySize, gemm_smem);
    cudaFuncSetAttribute(attn_h_kernel,
                         cudaFuncAttributeMaxDynamicSharedMemorySize, attn_smem);

    // 1) QKV projection: M=8192, N=3072 (fp16 tensor cores)
    mma_gemm<3072, 0, 0><<<dim3(24, 64), 256, gemm_smem>>>(x, w_qkv, nullptr);

    // 2) causal flash attention (fp16 tensor cores)
    attn_h_kernel<<<dim3(32, 64), 256, attn_smem>>>();

    // 3) output projection: M=8192, N=1024 (fp16, A = g_ctx)
    mma_gemm<1024, 1, 1><<<dim3(8, 64), 256, gemm_smem>>>(nullptr, w_out, out);
}

// round 14
// speedup vs baseline: 1.0551x; 1.0551x over previous
#include <cuda_runtime.h>
#include <cuda_fp16.h>
#include <math.h>
#include <stdint.h>

// Problem constants: B=4, T=2048, C=1024, H=16, D=64
#define QKV_ELEMS (4 * 16 * 2048 * 64)

__device__ float g_q[QKV_ELEMS];
__device__ float g_k[QKV_ELEMS];
__device__ float g_v[QKV_ELEMS];
__device__ float g_ctx[QKV_ELEMS];

__device__ __forceinline__ uint32_t pack2h(float a, float b) {
    half2 h = __floats2half2_rn(a, b);   // low = a, high = b
    return *reinterpret_cast<uint32_t*>(&h);
}

__device__ __forceinline__ uint32_t smem_u32(const void* p) {
    uint32_t a;
    asm("{ .reg .u64 t; cvta.to.shared.u64 t, %1; cvt.u32.u64 %0, t; }"
        : "=r"(a) : "l"(p));
    return a;
}

__device__ __forceinline__ void mma_f16(float c[4],
                                        uint32_t a0, uint32_t a1, uint32_t a2, uint32_t a3,
                                        uint32_t b0, uint32_t b1) {
    asm volatile(
        "mma.sync.aligned.m16n8k16.row.col.f32.f16.f16.f32 "
        "{%0,%1,%2,%3}, {%4,%5,%6,%7}, {%8,%9}, {%0,%1,%2,%3};"
        : "+f"(c[0]), "+f"(c[1]), "+f"(c[2]), "+f"(c[3])
        : "r"(a0), "r"(a1), "r"(a2), "r"(a3), "r"(b0), "r"(b1));
}

__device__ __forceinline__ void ldsm_x4(uint32_t* r, uint32_t addr) {
    asm volatile(
        "ldmatrix.sync.aligned.m8n8.x4.shared.b16 {%0,%1,%2,%3}, [%4];"
        : "=r"(r[0]), "=r"(r[1]), "=r"(r[2]), "=r"(r[3]) : "r"(addr));
}

// ---------------------------------------------------------------------------
// fp16 tensor-core GEMM: C[M,N] = A[M,K=1024] @ W[1024,N]
// 512 threads (16 warps, 4m x 4n), CTA tile 128x128, Kchunk 64 (16 iters,
// 64 MMAs per sync), ldmatrix.x4 fragment loads (conflict-free, stride 36w).
// SRC_CTX=1: A = g_ctx. EPI=0: scatter q/k/v. EPI=1: row-major out.
// ---------------------------------------------------------------------------
template <int N, int EPI, int SRC_CTX>
__global__ void __launch_bounds__(512) mma_gemm(const float* __restrict__ Ain,
                                                const float* __restrict__ W,
                                                float* __restrict__ out)
{
    const int K = 1024;
    const int LDH = 36;              // row stride in half2 words (32 payload + 4)
    const int BUF = 128 * LDH;       // 4608 words per operand buffer
    extern __shared__ uint32_t sh[];
    uint32_t* As = sh;               // 2 * BUF
    uint32_t* Bs = sh + 2 * BUF;     // 2 * BUF

    const float* A = SRC_CTX ? (const float*)g_ctx : Ain;

    int tid = threadIdx.x;
    int lane = tid & 31;
    int wid = tid >> 5;
    int wm = wid & 3;                // 32-row slab
    int wn = wid >> 2;               // 32-col slab
    int brow = blockIdx.y * 128;
    int bcol = blockIdx.x * 128;

    float c[2][4][4];
#pragma unroll
    for (int mt = 0; mt < 2; mt++)
#pragma unroll
        for (int nt = 0; nt < 4; nt++)
#pragma unroll
            for (int e = 0; e < 4; e++) c[mt][nt][e] = 0.f;

    // staging maps
    int a_r  = tid >> 2;             // 0..127
    int a_kq = tid & 3;              // 16-k chunk
    int b_n  = tid & 127;
    int b_kq = tid >> 7;             // 0..3, 16-k chunk

    const float* Ap = A + (size_t)(brow + a_r) * K + a_kq * 16;
    const float* Wp = W + bcol + b_n;

    uint32_t aw[8], bw[8];

#define LDG_TILE(kt)                                                         \
    {                                                                        \
        int k0 = (kt) * 64;                                                  \
        _Pragma("unroll")                                                    \
        for (int i = 0; i < 4; i++) {                                        \
            float4 v = *(const float4*)(Ap + k0 + i * 4);                    \
            aw[2 * i + 0] = pack2h(v.x, v.y);                                \
            aw[2 * i + 1] = pack2h(v.z, v.w);                                \
        }                                                                    \
        _Pragma("unroll")                                                    \
        for (int j = 0; j < 8; j++)                                          \
            bw[j] = pack2h(Wp[(size_t)(k0 + b_kq * 16 + 2 * j) * N],         \
                           Wp[(size_t)(k0 + b_kq * 16 + 2 * j + 1) * N]);    \
    }

#define STS_TILE(p)                                                         \
    {                                                                       \
        uint32_t* as = As + (p) * BUF + a_r * LDH + a_kq * 8;               \
        uint32_t* bs = Bs + (p) * BUF + b_n * LDH + b_kq * 8;               \
        *(uint4*)&as[0] = *(uint4*)&aw[0];                                  \
        *(uint4*)&as[4] = *(uint4*)&aw[4];                                  \
        *(uint4*)&bs[0] = *(uint4*)&bw[0];                                  \
        *(uint4*)&bs[4] = *(uint4*)&bw[4];                                  \
    }

    // ldmatrix per-lane addressing
    uint32_t sbase = smem_u32(sh);
    int a_row_l  = (lane & 7) + 8 * ((lane >> 3) & 1);
    int a_word_l = 4 * (lane >> 4);
    int b_row_l  = (lane & 7) + 8 * (lane >> 4);
    int b_word_l = 4 * ((lane >> 3) & 1);
    uint32_t aaddr0 = sbase + ((wm * 32 + a_row_l) * LDH + a_word_l) * 4;
    uint32_t baddr0 = sbase + 2 * BUF * 4 + ((wn * 32 + b_row_l) * LDH + b_word_l) * 4;

    LDG_TILE(0);
    STS_TILE(0);
    __syncthreads();

    for (int kt = 0; kt < 16; kt++) {
        int p = kt & 1;
        if (kt + 1 < 16) LDG_TILE(kt + 1);

        uint32_t abase = aaddr0 + p * BUF * 4;
        uint32_t bbase = baddr0 + p * BUF * 4;
#pragma unroll
        for (int ks = 0; ks < 4; ks++) {
            uint32_t a[2][4], b[2][4];
#pragma unroll
            for (int mt = 0; mt < 2; mt++)
                ldsm_x4(a[mt], abase + mt * (16 * LDH * 4) + ks * 32);
#pragma unroll
            for (int np = 0; np < 2; np++)
                ldsm_x4(b[np], bbase + np * (16 * LDH * 4) + ks * 32);
#pragma unroll
            for (int mt = 0; mt < 2; mt++)
#pragma unroll
                for (int np = 0; np < 2; np++) {
                    mma_f16(c[mt][2 * np + 0], a[mt][0], a[mt][1], a[mt][2], a[mt][3],
                            b[np][0], b[np][1]);
                    mma_f16(c[mt][2 * np + 1], a[mt][0], a[mt][1], a[mt][2], a[mt][3],
                            b[np][2], b[np][3]);
                }
        }

        if (kt + 1 < 16) STS_TILE((kt + 1) & 1);
        __syncthreads();
    }
#undef LDG_TILE
#undef STS_TILE

    // epilogue
    int row0 = brow + wm * 32 + (lane >> 2);
    int col0 = bcol + wn * 32 + (lane & 3) * 2;

    if (EPI == 0) {
        int which = bcol >> 10;
        float* dst = (which == 0) ? g_q : ((which == 1) ? g_k : g_v);
#pragma unroll
        for (int mt = 0; mt < 2; mt++) {
#pragma unroll
            for (int nt = 0; nt < 4; nt++) {
                int col = col0 + nt * 8;
                int cc = col & 1023;
                int h = cc >> 6, d = cc & 63;
#pragma unroll
                for (int half = 0; half < 2; half++) {
                    int r = row0 + mt * 16 + half * 8;
                    int bb = r >> 11, t = r & 2047;
                    float2 v;
                    v.x = c[mt][nt][half * 2 + 0];
                    v.y = c[mt][nt][half * 2 + 1];
                    *(float2*)&dst[((((size_t)bb * 16 + h) * 2048 + t) << 6) + d] = v;
                }
            }
        }
    } else {
#pragma unroll
        for (int mt = 0; mt < 2; mt++) {
#pragma unroll
            for (int nt = 0; nt < 4; nt++) {
                int col = col0 + nt * 8;
#pragma unroll
                for (int half = 0; half < 2; half++) {
                    int r = row0 + mt * 16 + half * 8;
                    float2 v;
                    v.x = c[mt][nt][half * 2 + 0];
                    v.y = c[mt][nt][half * 2 + 1];
                    *(float2*)&out[(size_t)r * N + col] = v;
                }
            }
        }
    }
}

// ---------------------------------------------------------------------------
// Causal flash attention, fp16 tensor cores (unchanged from R10 — passing).
// ---------------------------------------------------------------------------
__global__ void __launch_bounds__(256) attn_h_kernel()
{
    extern __shared__ uint32_t sm[];
    const int LDH = 36;
    uint32_t* Qh = sm;
    uint32_t* Kh = sm + 2304;
    uint32_t* Vt = sm + 4608;
    uint32_t* Ph = sm + 6912;
    float*    Ss = (float*)(sm + 9216);
    float* sm_m    = (float*)(sm + 13568);
    float* sm_l    = sm_m + 64;
    float* sm_corr = sm_m + 128;

    int bh = blockIdx.y;
    int qt = gridDim.x - 1 - blockIdx.x;
    int h = bh & 15, bb = bh >> 4;

    const float* Qp = g_q + ((size_t)bh * 2048 + qt * 64) * 64;
    const float* Kp = g_k + (size_t)bh * 2048 * 64;
    const float* Vp = g_v + (size_t)bh * 2048 * 64;

    int tid = threadIdx.x;
    int lane = tid & 31;
    int wid = tid >> 5;
    int wm = wid & 3;
    int wn = wid >> 2;
    int g = lane >> 2;
    int t = lane & 3;

    int r4 = tid >> 2;
    int c4 = tid & 3;

    {
        const float* qr = Qp + r4 * 64 + c4 * 16;
        uint32_t w[8];
#pragma unroll
        for (int f = 0; f < 4; f++) {
            float4 v = *(const float4*)(qr + f * 4);
            w[2 * f + 0] = pack2h(v.x, v.y);
            w[2 * f + 1] = pack2h(v.z, v.w);
        }
        *(uint4*)&Qh[r4 * LDH + c4 * 8]     = *(uint4*)&w[0];
        *(uint4*)&Qh[r4 * LDH + c4 * 8 + 4] = *(uint4*)&w[4];
    }
    if (tid < 64) {
        sm_m[tid] = -1e30f;
        sm_l[tid] = 0.f;
    }

    float o[4][4];
#pragma unroll
    for (int nt = 0; nt < 4; nt++)
#pragma unroll
        for (int e = 0; e < 4; e++) o[nt][e] = 0.f;

    const float scale = 0.125f;
    int arow = 16 * wm + g;

    int v_kp = 4 * wid + (lane & 3);
    int v_d0 = lane >> 2;

    for (int kt = 0; kt <= qt; kt++) {
        __syncthreads();
        {
            const float* kr = Kp + (size_t)(kt * 64 + r4) * 64 + c4 * 16;
            uint32_t w[8];
#pragma unroll
            for (int f = 0; f < 4; f++) {
                float4 v = *(const float4*)(kr + f * 4);
                w[2 * f + 0] = pack2h(v.x, v.y);
                w[2 * f + 1] = pack2h(v.z, v.w);
            }
            *(uint4*)&Kh[r4 * LDH + c4 * 8]     = *(uint4*)&w[0];
            *(uint4*)&Kh[r4 * LDH + c4 * 8 + 4] = *(uint4*)&w[4];
        }
        {
            const float* v0p = Vp + (size_t)(kt * 64 + 2 * v_kp) * 64;
            const float* v1p = v0p + 64;
#pragma unroll
            for (int j = 0; j < 8; j++) {
                int d = v_d0 + 8 * j;
                Vt[d * LDH + v_kp] = pack2h(v0p[d], v1p[d]);
            }
        }
        __syncthreads();

        float cs[4][4];
#pragma unroll
        for (int nt = 0; nt < 4; nt++)
#pragma unroll
            for (int e = 0; e < 4; e++) cs[nt][e] = 0.f;

#pragma unroll
        for (int ks = 0; ks < 4; ks++) {
            int k0 = ks * 8 + t;
            uint32_t a0 = Qh[arow * LDH + k0];
            uint32_t a1 = Qh[(arow + 8) * LDH + k0];
            uint32_t a2 = Qh[arow * LDH + k0 + 4];
            uint32_t a3 = Qh[(arow + 8) * LDH + k0 + 4];
#pragma unroll
            for (int nt = 0; nt < 4; nt++) {
                int n = 32 * wn + nt * 8 + g;
                uint32_t b0 = Kh[n * LDH + k0];
                uint32_t b1 = Kh[n * LDH + k0 + 4];
                mma_f16(cs[nt], a0, a1, a2, a3, b0, b1);
            }
        }

#pragma unroll
        for (int nt = 0; nt < 4; nt++) {
            int col = 32 * wn + nt * 8 + 2 * t;
            *(float2*)&Ss[arow * 68 + col] =
                make_float2(cs[nt][0] * scale, cs[nt][1] * scale);
            *(float2*)&Ss[(arow + 8) * 68 + col] =
                make_float2(cs[nt][2] * scale, cs[nt][3] * scale);
        }
        __syncthreads();

        {
            int r = r4;
            int c0 = c4 * 16;
            float* row = &Ss[r * 68];
            bool diag = (kt == qt);
            float v[16];
#pragma unroll
            for (int f = 0; f < 4; f++) {
                float4 x = *(float4*)&row[c0 + f * 4];
                v[f * 4 + 0] = x.x; v[f * 4 + 1] = x.y;
                v[f * 4 + 2] = x.z; v[f * 4 + 3] = x.w;
            }
            if (diag) {
#pragma unroll
                for (int j = 0; j < 16; j++)
                    if (c0 + j > r) v[j] = -1e30f;
            }
            float mx = v[0];
#pragma unroll
            for (int j = 1; j < 16; j++) mx = fmaxf(mx, v[j]);
            mx = fmaxf(mx, __shfl_xor_sync(0xffffffffu, mx, 1));
            mx = fmaxf(mx, __shfl_xor_sync(0xffffffffu, mx, 2));
            float mprev = sm_m[r];
            float nm = fmaxf(mprev, mx);
            float sum = 0.f;
#pragma unroll
            for (int j = 0; j < 16; j++) {
                v[j] = __expf(v[j] - nm);
                sum += v[j];
            }
            uint32_t pw[8];
#pragma unroll
            for (int j = 0; j < 8; j++)
                pw[j] = pack2h(v[2 * j], v[2 * j + 1]);
            *(uint4*)&Ph[r * LDH + c4 * 8]     = *(uint4*)&pw[0];
            *(uint4*)&Ph[r * LDH + c4 * 8 + 4] = *(uint4*)&pw[4];
            sum += __shfl_xor_sync(0xffffffffu, sum, 1);
            sum += __shfl_xor_sync(0xffffffffu, sum, 2);
            if (c4 == 0) {
                float corr = __expf(mprev - nm);
                sm_l[r] = sm_l[r] * corr + sum;
                sm_m[r] = nm;
                sm_corr[r] = corr;
            }
        }
        __syncthreads();

        {
            float cr0 = sm_corr[arow];
            float cr1 = sm_corr[arow + 8];
#pragma unroll
            for (int nt = 0; nt < 4; nt++) {
                o[nt][0] *= cr0; o[nt][1] *= cr0;
                o[nt][2] *= cr1; o[nt][3] *= cr1;
            }
#pragma unroll
            for (int ks = 0; ks < 4; ks++) {
                int k0 = ks * 8 + t;
                uint32_t a0 = Ph[arow * LDH + k0];
                uint32_t a1 = Ph[(arow + 8) * LDH + k0];
                uint32_t a2 = Ph[arow * LDH + k0 + 4];
                uint32_t a3 = Ph[(arow + 8) * LDH + k0 + 4];
#pragma unroll
                for (int nt = 0; nt < 4; nt++) {
                    int n = 32 * wn + nt * 8 + g;
                    uint32_t b0 = Vt[n * LDH + k0];
                    uint32_t b1 = Vt[n * LDH + k0 + 4];
                    mma_f16(o[nt], a0, a1, a2, a3, b0, b1);
                }
            }
        }
    }

    {
        float il0 = 1.f / sm_l[arow];
        float il1 = 1.f / sm_l[arow + 8];
        int q0 = qt * 64 + arow;
#pragma unroll
        for (int nt = 0; nt < 4; nt++) {
            int dcol = 32 * wn + nt * 8 + 2 * t;
            *(float2*)&g_ctx[((size_t)bb * 2048 + q0) * 1024 + h * 64 + dcol] =
                make_float2(o[nt][0] * il0, o[nt][1] * il0);
            *(float2*)&g_ctx[((size_t)bb * 2048 + q0 + 8) * 1024 + h * 64 + dcol] =
                make_float2(o[nt][2] * il1, o[nt][3] * il1);
        }
    }
}

// ---------------------------------------------------------------------------
extern "C" void kernel_launch(void* const* d_in, const int* in_sizes, int n_in,
                              void* d_out, int out_size)
{
    const float* x     = (const float*)d_in[0];  // [4,2048,1024]
    const float* w_qkv = (const float*)d_in[1];  // [1024,3072]
    const float* w_out = (const float*)d_in[2];  // [1024,1024]
    float* out = (float*)d_out;                  // [4,2048,1024]

    (void)in_sizes; (void)n_in; (void)out_size;

    const int gemm_smem = 4 * 128 * 36 * (int)sizeof(uint32_t);  // 73728
    const int attn_smem = 13760 * (int)sizeof(uint32_t);         // 55040

    cudaFuncSetAttribute(mma_gemm<3072, 0, 0>,
                         cudaFuncAttributeMaxDynamicSharedMemorySize, gemm_smem);
    cudaFuncSetAttribute(mma_gemm<1024, 1, 1>,
                         cudaFuncAttributeMaxDynamicSharedMemorySize, gemm_smem);
    cudaFuncSetAttribute(attn_h_kernel,
                         cudaFuncAttributeMaxDynamicSharedMemorySize, attn_smem);

    // 1) QKV projection: M=8192, N=3072 (fp16, Kchunk=64, ldmatrix)
    mma_gemm<3072, 0, 0><<<dim3(24, 64), 512, gemm_smem>>>(x, w_qkv, nullptr);

    // 2) causal flash attention (fp16 tensor cores)
    attn_h_kernel<<<dim3(32, 64), 256, attn_smem>>>();

    // 3) output projection: M=8192, N=1024 (fp16, A = g_ctx)
    mma_gemm<1024, 1, 1><<<dim3(8, 64), 512, gemm_smem>>>(nullptr, w_out, out);
}

// round 15
// speedup vs baseline: 1.6209x; 1.5362x over previous
#include <cuda_runtime.h>
#include <cuda_fp16.h>
#include <math.h>
#include <stdint.h>

// Problem constants: B=4, T=2048, C=1024, H=16, D=64
#define QKV_ELEMS (4 * 16 * 2048 * 64)

__device__ __half g_xh[QKV_ELEMS];        // x as fp16 [8192,1024]
__device__ __half g_wqkvT[3072 * 1024];   // w_qkv^T fp16 [n][k]
__device__ __half g_woutT[1024 * 1024];   // w_out^T fp16 [n][k]
__device__ __half g_qh[QKV_ELEMS];        // [B,H,T,D] fp16
__device__ __half g_kh[QKV_ELEMS];
__device__ __half g_vh[QKV_ELEMS];
__device__ __half g_ctxh[QKV_ELEMS];      // ctx fp16 [8192,1024]

__device__ __forceinline__ uint32_t pack2h(float a, float b) {
    half2 h = __floats2half2_rn(a, b);   // low = a, high = b
    return *reinterpret_cast<uint32_t*>(&h);
}

__device__ __forceinline__ uint32_t smem_u32(const void* p) {
    uint32_t a;
    asm("{ .reg .u64 t; cvta.to.shared.u64 t, %1; cvt.u32.u64 %0, t; }"
        : "=r"(a) : "l"(p));
    return a;
}

__device__ __forceinline__ void mma_f16(float c[4],
                                        uint32_t a0, uint32_t a1, uint32_t a2, uint32_t a3,
                                        uint32_t b0, uint32_t b1) {
    asm volatile(
        "mma.sync.aligned.m16n8k16.row.col.f32.f16.f16.f32 "
        "{%0,%1,%2,%3}, {%4,%5,%6,%7}, {%8,%9}, {%0,%1,%2,%3};"
        : "+f"(c[0]), "+f"(c[1]), "+f"(c[2]), "+f"(c[3])
        : "r"(a0), "r"(a1), "r"(a2), "r"(a3), "r"(b0), "r"(b1));
}

__device__ __forceinline__ void ldsm_x4(uint32_t* r, uint32_t addr) {
    asm volatile(
        "ldmatrix.sync.aligned.m8n8.x4.shared.b16 {%0,%1,%2,%3}, [%4];"
        : "=r"(r[0]), "=r"(r[1]), "=r"(r[2]), "=r"(r[3]) : "r"(addr));
}

__device__ __forceinline__ void cp16(uint32_t dst, const void* src) {
    asm volatile("cp.async.cg.shared.global [%0], [%1], 16;"
                 :: "r"(dst), "l"(src));
}
#define CP_COMMIT() asm volatile("cp.async.commit_group;" ::: "memory")
#define CP_WAIT1()  asm volatile("cp.async.wait_group 1;" ::: "memory")

// ---------------------------------------------------------------------------
// Conversion pre-passes
// ---------------------------------------------------------------------------
__global__ void conv_x_kernel(const float* __restrict__ x)
{
    int i = blockIdx.x * blockDim.x + threadIdx.x;   // over float4s
    float4 v = ((const float4*)x)[i];
    uint2 o;
    o.x = pack2h(v.x, v.y);
    o.y = pack2h(v.z, v.w);
    ((uint2*)g_xh)[i] = o;
}

// W [1024, Ncols] f32 -> WT [Ncols, 1024] fp16
template <int NCOLS>
__global__ void convT_kernel(const float* __restrict__ W, int which)
{
    __shared__ float tile[32][33];
    __half* WT = which ? g_woutT : g_wqkvT;
    int bx = blockIdx.x * 32;   // over Ncols
    int by = blockIdx.y * 32;   // over K=1024
    int tx = threadIdx.x & 31, ty = threadIdx.x >> 5;
#pragma unroll
    for (int i = 0; i < 4; i++)
        tile[ty + 8 * i][tx] = W[(size_t)(by + ty + 8 * i) * NCOLS + bx + tx];
    __syncthreads();
#pragma unroll
    for (int i = 0; i < 4; i++)
        WT[(size_t)(bx + ty + 8 * i) * 1024 + by + tx] =
            __float2half(tile[tx][ty + 8 * i]);
}

// ---------------------------------------------------------------------------
// fp16 GEMM with cp.async 3-stage pipeline.
// C[M,N] = A[M,1024] @ B^T  (B stored [n][k] fp16).
// 512 threads (16 warps, 4m x 4n), CTA 128x128, Kchunk 64, rows 72 halfs
// (LDH=36 words) — same conflict-free ldmatrix mapping as R14.
// EPI 0: scatter fp16 q/k/v.  EPI 1: fp32 row-major out.
// ---------------------------------------------------------------------------
template <int EPI>
__global__ void __launch_bounds__(512, 2) hgemm(float* __restrict__ out)
{
    const int K = 1024;
    const int N = (EPI == 0) ? 3072 : 1024;
    const __half* A = (EPI == 0) ? g_xh : g_ctxh;
    const __half* B = (EPI == 0) ? g_wqkvT : g_woutT;

    const int LDH = 36;               // words per row (72 halfs = 144B)
    const int OPW = 128 * LDH;        // 4608 words per operand
    const int STW = 2 * OPW;          // 9216 words per stage
    extern __shared__ uint32_t sh[];  // 3 stages = 110592 B

    int tid = threadIdx.x;
    int lane = tid & 31;
    int wid = tid >> 5;
    int wm = wid & 3;
    int wn = wid >> 2;
    int brow = blockIdx.y * 128;
    int bcol = blockIdx.x * 128;

    float c[2][4][4];
#pragma unroll
    for (int mt = 0; mt < 2; mt++)
#pragma unroll
        for (int nt = 0; nt < 4; nt++)
#pragma unroll
            for (int e = 0; e < 4; e++) c[mt][nt][e] = 0.f;

    uint32_t sbase = smem_u32(sh);

    // copy chunks: 1024 chunks of 16B per operand per stage; thread does
    // chunks {tid, tid+512} for both A and B.
    int r0c = tid >> 3,         cc0 = tid & 7;
    int r1c = (tid + 512) >> 3, cc1 = (tid + 512) & 7;
    const __half* Asrc0 = A + (size_t)(brow + r0c) * K + cc0 * 8;
    const __half* Asrc1 = A + (size_t)(brow + r1c) * K + cc1 * 8;
    const __half* Bsrc0 = B + (size_t)(bcol + r0c) * K + cc0 * 8;
    const __half* Bsrc1 = B + (size_t)(bcol + r1c) * K + cc1 * 8;
    uint32_t Adst0 = sbase + (r0c * LDH + cc0 * 4) * 4;
    uint32_t Adst1 = sbase + (r1c * LDH + cc1 * 4) * 4;
    uint32_t Bdst0 = Adst0 + OPW * 4;
    uint32_t Bdst1 = Adst1 + OPW * 4;

#define ISSUE(kt_, s_)                                                       \
    {                                                                        \
        int k0 = (kt_) * 64;                                                 \
        uint32_t so = (uint32_t)(s_) * STW * 4;                              \
        cp16(Adst0 + so, Asrc0 + k0);                                        \
        cp16(Adst1 + so, Asrc1 + k0);                                        \
        cp16(Bdst0 + so, Bsrc0 + k0);                                        \
        cp16(Bdst1 + so, Bsrc1 + k0);                                        \
    }

    // ldmatrix per-lane addressing (identical mapping to R14)
    int a_row_l  = (lane & 7) + 8 * ((lane >> 3) & 1);
    int a_word_l = 4 * (lane >> 4);
    int b_row_l  = (lane & 7) + 8 * (lane >> 4);
    int b_word_l = 4 * ((lane >> 3) & 1);
    uint32_t aaddr0 = sbase + ((wm * 32 + a_row_l) * LDH + a_word_l) * 4;
    uint32_t baddr0 = sbase + OPW * 4 + ((wn * 32 + b_row_l) * LDH + b_word_l) * 4;

    ISSUE(0, 0); CP_COMMIT();
    ISSUE(1, 1); CP_COMMIT();

    for (int kt = 0; kt < 16; kt++) {
        int s = kt % 3;
        CP_WAIT1();
        __syncthreads();

        uint32_t abase = aaddr0 + s * STW * 4;
        uint32_t bbase = baddr0 + s * STW * 4;
#pragma unroll
        for (int ks = 0; ks < 4; ks++) {
            uint32_t a[2][4], b[2][4];
#pragma unroll
            for (int mt = 0; mt < 2; mt++)
                ldsm_x4(a[mt], abase + mt * (16 * LDH * 4) + ks * 32);
#pragma unroll
            for (int np = 0; np < 2; np++)
                ldsm_x4(b[np], bbase + np * (16 * LDH * 4) + ks * 32);
#pragma unroll
            for (int mt = 0; mt < 2; mt++)
#pragma unroll
                for (int np = 0; np < 2; np++) {
                    mma_f16(c[mt][2 * np + 0], a[mt][0], a[mt][1], a[mt][2], a[mt][3],
                            b[np][0], b[np][1]);
                    mma_f16(c[mt][2 * np + 1], a[mt][0], a[mt][1], a[mt][2], a[mt][3],
                            b[np][2], b[np][3]);
                }
        }

        if (kt + 2 < 16) ISSUE(kt + 2, (kt + 2) % 3);
        CP_COMMIT();
    }
#undef ISSUE

    // epilogue
    int row0 = brow + wm * 32 + (lane >> 2);
    int col0 = bcol + wn * 32 + (lane & 3) * 2;

    if (EPI == 0) {
        int which = bcol >> 10;
        __half* dst = (which == 0) ? g_qh : ((which == 1) ? g_kh : g_vh);
#pragma unroll
        for (int mt = 0; mt < 2; mt++) {
#pragma unroll
            for (int nt = 0; nt < 4; nt++) {
                int col = col0 + nt * 8;
                int cc = col & 1023;
                int h = cc >> 6, d = cc & 63;
#pragma unroll
                for (int hf = 0; hf < 2; hf++) {
                    int r = row0 + mt * 16 + hf * 8;
                    int bb = r >> 11, t = r & 2047;
                    uint32_t p = pack2h(c[mt][nt][hf * 2], c[mt][nt][hf * 2 + 1]);
                    *(uint32_t*)&dst[((((size_t)bb * 16 + h) * 2048 + t) << 6) + d] = p;
                }
            }
        }
    } else {
#pragma unroll
        for (int mt = 0; mt < 2; mt++) {
#pragma unroll
            for (int nt = 0; nt < 4; nt++) {
                int col = col0 + nt * 8;
#pragma unroll
                for (int hf = 0; hf < 2; hf++) {
                    int r = row0 + mt * 16 + hf * 8;
                    float2 v;
                    v.x = c[mt][nt][hf * 2 + 0];
                    v.y = c[mt][nt][hf * 2 + 1];
                    *(float2*)&out[(size_t)r * N + col] = v;
                }
            }
        }
    }
}

// ---------------------------------------------------------------------------
// Causal flash attention, fp16 tensor cores; q/k/v/ctx now fp16 in gmem.
// Structure identical to the passing R10/R14 kernel; staging simplified to
// raw uint4 copies (no conversion).
// ---------------------------------------------------------------------------
__global__ void __launch_bounds__(256) attn_h_kernel()
{
    extern __shared__ uint32_t sm[];
    const int LDH = 36;
    uint32_t* Qh = sm;
    uint32_t* Kh = sm + 2304;
    uint32_t* Vt = sm + 4608;
    uint32_t* Ph = sm + 6912;
    float*    Ss = (float*)(sm + 9216);
    float* sm_m    = (float*)(sm + 13568);
    float* sm_l    = sm_m + 64;
    float* sm_corr = sm_m + 128;

    int bh = blockIdx.y;
    int qt = gridDim.x - 1 - blockIdx.x;
    int h = bh & 15, bb = bh >> 4;

    const __half* Qp = g_qh + ((size_t)bh * 2048 + qt * 64) * 64;
    const __half* Kp = g_kh + (size_t)bh * 2048 * 64;
    const __half* Vp = g_vh + (size_t)bh * 2048 * 64;

    int tid = threadIdx.x;
    int lane = tid & 31;
    int wid = tid >> 5;
    int wm = wid & 3;
    int wn = wid >> 2;
    int g = lane >> 2;
    int t = lane & 3;

    int r4 = tid >> 2;
    int c4 = tid & 3;

    // Q staging: raw copy of 16 halfs per thread
    {
        const uint4* qr = (const uint4*)(Qp + r4 * 64 + c4 * 16);
        *(uint4*)&Qh[r4 * LDH + c4 * 8]     = qr[0];
        *(uint4*)&Qh[r4 * LDH + c4 * 8 + 4] = qr[1];
    }
    if (tid < 64) {
        sm_m[tid] = -1e30f;
        sm_l[tid] = 0.f;
    }

    float o[4][4];
#pragma unroll
    for (int nt = 0; nt < 4; nt++)
#pragma unroll
        for (int e = 0; e < 4; e++) o[nt][e] = 0.f;

    const float scale = 0.125f;
    int arow = 16 * wm + g;

    int v_kp = 4 * wid + (lane & 3);
    int v_d0 = lane >> 2;

    for (int kt = 0; kt <= qt; kt++) {
        __syncthreads();
        {
            const uint4* kr = (const uint4*)(Kp + (size_t)(kt * 64 + r4) * 64 + c4 * 16);
            *(uint4*)&Kh[r4 * LDH + c4 * 8]     = kr[0];
            *(uint4*)&Kh[r4 * LDH + c4 * 8 + 4] = kr[1];
        }
        {
            const __half* v0p = Vp + (size_t)(kt * 64 + 2 * v_kp) * 64;
            const __half* v1p = v0p + 64;
#pragma unroll
            for (int j = 0; j < 8; j++) {
                int d = v_d0 + 8 * j;
                half2 h2 = __halves2half2(v0p[d], v1p[d]);
                Vt[d * LDH + v_kp] = *reinterpret_cast<uint32_t*>(&h2);
            }
        }
        __syncthreads();

        float cs[4][4];
#pragma unroll
        for (int nt = 0; nt < 4; nt++)
#pragma unroll
            for (int e = 0; e < 4; e++) cs[nt][e] = 0.f;

#pragma unroll
        for (int ks = 0; ks < 4; ks++) {
            int k0 = ks * 8 + t;
            uint32_t a0 = Qh[arow * LDH + k0];
            uint32_t a1 = Qh[(arow + 8) * LDH + k0];
            uint32_t a2 = Qh[arow * LDH + k0 + 4];
            uint32_t a3 = Qh[(arow + 8) * LDH + k0 + 4];
#pragma unroll
            for (int nt = 0; nt < 4; nt++) {
                int n = 32 * wn + nt * 8 + g;
                uint32_t b0 = Kh[n * LDH + k0];
                uint32_t b1 = Kh[n * LDH + k0 + 4];
                mma_f16(cs[nt], a0, a1, a2, a3, b0, b1);
            }
        }

#pragma unroll
        for (int nt = 0; nt < 4; nt++) {
            int col = 32 * wn + nt * 8 + 2 * t;
            *(float2*)&Ss[arow * 68 + col] =
                make_float2(cs[nt][0] * scale, cs[nt][1] * scale);
            *(float2*)&Ss[(arow + 8) * 68 + col] =
                make_float2(cs[nt][2] * scale, cs[nt][3] * scale);
        }
        __syncthreads();

        {
            int r = r4;
            int c0 = c4 * 16;
            float* row = &Ss[r * 68];
            bool diag = (kt == qt);
            float v[16];
#pragma unroll
            for (int f = 0; f < 4; f++) {
                float4 x = *(float4*)&row[c0 + f * 4];
                v[f * 4 + 0] = x.x; v[f * 4 + 1] = x.y;
                v[f * 4 + 2] = x.z; v[f * 4 + 3] = x.w;
            }
            if (diag) {
#pragma unroll
                for (int j = 0; j < 16; j++)
                    if (c0 + j > r) v[j] = -1e30f;
            }
            float mx = v[0];
#pragma unroll
            for (int j = 1; j < 16; j++) mx = fmaxf(mx, v[j]);
            mx = fmaxf(mx, __shfl_xor_sync(0xffffffffu, mx, 1));
            mx = fmaxf(mx, __shfl_xor_sync(0xffffffffu, mx, 2));
            float mprev = sm_m[r];
            float nm = fmaxf(mprev, mx);
            float sum = 0.f;
#pragma unroll
            for (int j = 0; j < 16; j++) {
                v[j] = __expf(v[j] - nm);
                sum += v[j];
            }
            uint32_t pw[8];
#pragma unroll
            for (int j = 0; j < 8; j++)
                pw[j] = pack2h(v[2 * j], v[2 * j + 1]);
            *(uint4*)&Ph[r * LDH + c4 * 8]     = *(uint4*)&pw[0];
            *(uint4*)&Ph[r * LDH + c4 * 8 + 4] = *(uint4*)&pw[4];
            sum += __shfl_xor_sync(0xffffffffu, sum, 1);
            sum += __shfl_xor_sync(0xffffffffu, sum, 2);
            if (c4 == 0) {
                float corr = __expf(mprev - nm);
                sm_l[r] = sm_l[r] * corr + sum;
                sm_m[r] = nm;
                sm_corr[r] = corr;
            }
        }
        __syncthreads();

        {
            float cr0 = sm_corr[arow];
            float cr1 = sm_corr[arow + 8];
#pragma unroll
            for (int nt = 0; nt < 4; nt++) {
                o[nt][0] *= cr0; o[nt][1] *= cr0;
                o[nt][2] *= cr1; o[nt][3] *= cr1;
            }
#pragma unroll
            for (int ks = 0; ks < 4; ks++) {
                int k0 = ks * 8 + t;
                uint32_t a0 = Ph[arow * LDH + k0];
                uint32_t a1 = Ph[(arow + 8) * LDH + k0];
                uint32_t a2 = Ph[arow * LDH + k0 + 4];
                uint32_t a3 = Ph[(arow + 8) * LDH + k0 + 4];
#pragma unroll
                for (int nt = 0; nt < 4; nt++) {
                    int n = 32 * wn + nt * 8 + g;
                    uint32_t b0 = Vt[n * LDH + k0];
                    uint32_t b1 = Vt[n * LDH + k0 + 4];
                    mma_f16(o[nt], a0, a1, a2, a3, b0, b1);
                }
            }
        }
    }

    // epilogue: normalize, write ctx as fp16
    {
        float il0 = 1.f / sm_l[arow];
        float il1 = 1.f / sm_l[arow + 8];
        int q0 = qt * 64 + arow;
#pragma unroll
        for (int nt = 0; nt < 4; nt++) {
            int dcol = 32 * wn + nt * 8 + 2 * t;
            *(uint32_t*)&g_ctxh[((size_t)bb * 2048 + q0) * 1024 + h * 64 + dcol] =
                pack2h(o[nt][0] * il0, o[nt][1] * il0);
            *(uint32_t*)&g_ctxh[((size_t)bb * 2048 + q0 + 8) * 1024 + h * 64 + dcol] =
                pack2h(o[nt][2] * il1, o[nt][3] * il1);
        }
    }
}

// ---------------------------------------------------------------------------
extern "C" void kernel_launch(void* const* d_in, const int* in_sizes, int n_in,
                              void* d_out, int out_size)
{
    const float* x     = (const float*)d_in[0];  // [4,2048,1024]
    const float* w_qkv = (const float*)d_in[1];  // [1024,3072]
    const float* w_out = (const float*)d_in[2];  // [1024,1024]
    float* out = (float*)d_out;                  // [4,2048,1024]

    (void)in_sizes; (void)n_in; (void)out_size;

    const int gemm_smem = 3 * 2 * 128 * 36 * 4;          // 110592
    const int attn_smem = 13760 * (int)sizeof(uint32_t); // 55040

    cudaFuncSetAttribute(hgemm<0>,
                         cudaFuncAttributeMaxDynamicSharedMemorySize, gemm_smem);
    cudaFuncSetAttribute(hgemm<1>,
                         cudaFuncAttributeMaxDynamicSharedMemorySize, gemm_smem);
    cudaFuncSetAttribute(attn_h_kernel,
                         cudaFuncAttributeMaxDynamicSharedMemorySize, attn_smem);

    // 0) conversions: x -> fp16; weights -> transposed fp16
    conv_x_kernel<<<QKV_ELEMS / 4 / 256, 256>>>(x);
    convT_kernel<3072><<<dim3(96, 32), 256>>>(w_qkv, 0);
    convT_kernel<1024><<<dim3(32, 32), 256>>>(w_out, 1);

    // 1) QKV projection: M=8192, N=3072
    hgemm<0><<<dim3(24, 64), 512, gemm_smem>>>(nullptr);

    // 2) causal flash attention (fp16)
    attn_h_kernel<<<dim3(32, 64), 256, attn_smem>>>();

    // 3) output projection: M=8192, N=1024
    hgemm<1><<<dim3(8, 64), 512, gemm_smem>>>(out);
}

// round 16
// speedup vs baseline: 2.4541x; 1.5141x over previous
#include <cuda_runtime.h>
#include <cuda_fp16.h>
#include <math.h>
#include <stdint.h>

// Problem constants: B=4, T=2048, C=1024, H=16, D=64
#define QKV_ELEMS (4 * 16 * 2048 * 64)

__device__ __half g_xh[QKV_ELEMS];        // x as fp16 [8192,1024]
__device__ __half g_wqkvT[3072 * 1024];   // w_qkv^T fp16 [n][k]
__device__ __half g_woutT[1024 * 1024];   // w_out^T fp16 [n][k]
__device__ __half g_qh[QKV_ELEMS];        // [B,H,T,D] fp16
__device__ __half g_kh[QKV_ELEMS];        // [B,H,T,D] fp16
__device__ __half g_vTh[QKV_ELEMS];       // V^T: [B,H,D,T] fp16
__device__ __half g_ctxh[QKV_ELEMS];      // ctx fp16 [8192,1024]

__device__ __forceinline__ uint32_t pack2h(float a, float b) {
    half2 h = __floats2half2_rn(a, b);   // low = a, high = b
    return *reinterpret_cast<uint32_t*>(&h);
}

__device__ __forceinline__ uint32_t smem_u32(const void* p) {
    uint32_t a;
    asm("{ .reg .u64 t; cvta.to.shared.u64 t, %1; cvt.u32.u64 %0, t; }"
        : "=r"(a) : "l"(p));
    return a;
}

__device__ __forceinline__ void mma_f16(float c[4],
                                        uint32_t a0, uint32_t a1, uint32_t a2, uint32_t a3,
                                        uint32_t b0, uint32_t b1) {
    asm volatile(
        "mma.sync.aligned.m16n8k16.row.col.f32.f16.f16.f32 "
        "{%0,%1,%2,%3}, {%4,%5,%6,%7}, {%8,%9}, {%0,%1,%2,%3};"
        : "+f"(c[0]), "+f"(c[1]), "+f"(c[2]), "+f"(c[3])
        : "r"(a0), "r"(a1), "r"(a2), "r"(a3), "r"(b0), "r"(b1));
}

__device__ __forceinline__ void ldsm_x4(uint32_t* r, uint32_t addr) {
    asm volatile(
        "ldmatrix.sync.aligned.m8n8.x4.shared.b16 {%0,%1,%2,%3}, [%4];"
        : "=r"(r[0]), "=r"(r[1]), "=r"(r[2]), "=r"(r[3]) : "r"(addr));
}

__device__ __forceinline__ void cp16(uint32_t dst, const void* src) {
    asm volatile("cp.async.cg.shared.global [%0], [%1], 16;"
                 :: "r"(dst), "l"(src));
}
#define CP_COMMIT() asm volatile("cp.async.commit_group;" ::: "memory")
#define CP_WAIT1()  asm volatile("cp.async.wait_group 1;" ::: "memory")
#define CP_WAIT0()  asm volatile("cp.async.wait_group 0;" ::: "memory")

// ---------------------------------------------------------------------------
// Conversion pre-passes
// ---------------------------------------------------------------------------
__global__ void conv_x_kernel(const float* __restrict__ x)
{
    int i = blockIdx.x * blockDim.x + threadIdx.x;   // over float4s
    float4 v = ((const float4*)x)[i];
    uint2 o;
    o.x = pack2h(v.x, v.y);
    o.y = pack2h(v.z, v.w);
    ((uint2*)g_xh)[i] = o;
}

// W [1024, Ncols] f32 -> WT [Ncols, 1024] fp16
template <int NCOLS>
__global__ void convT_kernel(const float* __restrict__ W, int which)
{
    __shared__ float tile[32][33];
    __half* WT = which ? g_woutT : g_wqkvT;
    int bx = blockIdx.x * 32;   // over Ncols
    int by = blockIdx.y * 32;   // over K=1024
    int tx = threadIdx.x & 31, ty = threadIdx.x >> 5;
#pragma unroll
    for (int i = 0; i < 4; i++)
        tile[ty + 8 * i][tx] = W[(size_t)(by + ty + 8 * i) * NCOLS + bx + tx];
    __syncthreads();
#pragma unroll
    for (int i = 0; i < 4; i++)
        WT[(size_t)(bx + ty + 8 * i) * 1024 + by + tx] =
            __float2half(tile[tx][ty + 8 * i]);
}

// ---------------------------------------------------------------------------
// fp16 GEMM with cp.async 3-stage pipeline (R15-passing; only the v-epilogue
// changed: v is written TRANSPOSED into g_vTh [bh][d][t]).
// ---------------------------------------------------------------------------
template <int EPI>
__global__ void __launch_bounds__(512, 2) hgemm(float* __restrict__ out)
{
    const int K = 1024;
    const int N = (EPI == 0) ? 3072 : 1024;
    const __half* A = (EPI == 0) ? g_xh : g_ctxh;
    const __half* B = (EPI == 0) ? g_wqkvT : g_woutT;

    const int LDH = 36;
    const int OPW = 128 * LDH;
    const int STW = 2 * OPW;
    extern __shared__ uint32_t sh[];

    int tid = threadIdx.x;
    int lane = tid & 31;
    int wid = tid >> 5;
    int wm = wid & 3;
    int wn = wid >> 2;
    int brow = blockIdx.y * 128;
    int bcol = blockIdx.x * 128;

    float c[2][4][4];
#pragma unroll
    for (int mt = 0; mt < 2; mt++)
#pragma unroll
        for (int nt = 0; nt < 4; nt++)
#pragma unroll
            for (int e = 0; e < 4; e++) c[mt][nt][e] = 0.f;

    uint32_t sbase = smem_u32(sh);

    int r0c = tid >> 3,         cc0 = tid & 7;
    int r1c = (tid + 512) >> 3, cc1 = (tid + 512) & 7;
    const __half* Asrc0 = A + (size_t)(brow + r0c) * K + cc0 * 8;
    const __half* Asrc1 = A + (size_t)(brow + r1c) * K + cc1 * 8;
    const __half* Bsrc0 = B + (size_t)(bcol + r0c) * K + cc0 * 8;
    const __half* Bsrc1 = B + (size_t)(bcol + r1c) * K + cc1 * 8;
    uint32_t Adst0 = sbase + (r0c * LDH + cc0 * 4) * 4;
    uint32_t Adst1 = sbase + (r1c * LDH + cc1 * 4) * 4;
    uint32_t Bdst0 = Adst0 + OPW * 4;
    uint32_t Bdst1 = Adst1 + OPW * 4;

#define ISSUE(kt_, s_)                                                       \
    {                                                                        \
        int k0 = (kt_) * 64;                                                 \
        uint32_t so = (uint32_t)(s_) * STW * 4;                              \
        cp16(Adst0 + so, Asrc0 + k0);                                        \
        cp16(Adst1 + so, Asrc1 + k0);                                        \
        cp16(Bdst0 + so, Bsrc0 + k0);                                        \
        cp16(Bdst1 + so, Bsrc1 + k0);                                        \
    }

    int a_row_l  = (lane & 7) + 8 * ((lane >> 3) & 1);
    int a_word_l = 4 * (lane >> 4);
    int b_row_l  = (lane & 7) + 8 * (lane >> 4);
    int b_word_l = 4 * ((lane >> 3) & 1);
    uint32_t aaddr0 = sbase + ((wm * 32 + a_row_l) * LDH + a_word_l) * 4;
    uint32_t baddr0 = sbase + OPW * 4 + ((wn * 32 + b_row_l) * LDH + b_word_l) * 4;

    ISSUE(0, 0); CP_COMMIT();
    ISSUE(1, 1); CP_COMMIT();

    for (int kt = 0; kt < 16; kt++) {
        int s = kt % 3;
        CP_WAIT1();
        __syncthreads();

        uint32_t abase = aaddr0 + s * STW * 4;
        uint32_t bbase = baddr0 + s * STW * 4;
#pragma unroll
        for (int ks = 0; ks < 4; ks++) {
            uint32_t a[2][4], b[2][4];
#pragma unroll
            for (int mt = 0; mt < 2; mt++)
                ldsm_x4(a[mt], abase + mt * (16 * LDH * 4) + ks * 32);
#pragma unroll
            for (int np = 0; np < 2; np++)
                ldsm_x4(b[np], bbase + np * (16 * LDH * 4) + ks * 32);
#pragma unroll
            for (int mt = 0; mt < 2; mt++)
#pragma unroll
                for (int np = 0; np < 2; np++) {
                    mma_f16(c[mt][2 * np + 0], a[mt][0], a[mt][1], a[mt][2], a[mt][3],
                            b[np][0], b[np][1]);
                    mma_f16(c[mt][2 * np + 1], a[mt][0], a[mt][1], a[mt][2], a[mt][3],
                            b[np][2], b[np][3]);
                }
        }

        if (kt + 2 < 16) ISSUE(kt + 2, (kt + 2) % 3);
        CP_COMMIT();
    }
#undef ISSUE

    int row0 = brow + wm * 32 + (lane >> 2);
    int col0 = bcol + wn * 32 + (lane & 3) * 2;

    if (EPI == 0) {
        int which = bcol >> 10;
        if (which == 2) {
            // V: write transposed into g_vTh [bh][d][t]
#pragma unroll
            for (int mt = 0; mt < 2; mt++) {
#pragma unroll
                for (int nt = 0; nt < 4; nt++) {
                    int col = col0 + nt * 8;
                    int cc = col & 1023;
                    int h = cc >> 6, d = cc & 63;
#pragma unroll
                    for (int hf = 0; hf < 2; hf++) {
                        int r = row0 + mt * 16 + hf * 8;
                        int bb = r >> 11, tt = r & 2047;
                        size_t base = ((size_t)(bb * 16 + h) * 64 + d) * 2048 + tt;
                        g_vTh[base]        = __float2half(c[mt][nt][hf * 2 + 0]);
                        g_vTh[base + 2048] = __float2half(c[mt][nt][hf * 2 + 1]);
                    }
                }
            }
        } else {
            __half* dst = (which == 0) ? g_qh : g_kh;
#pragma unroll
            for (int mt = 0; mt < 2; mt++) {
#pragma unroll
                for (int nt = 0; nt < 4; nt++) {
                    int col = col0 + nt * 8;
                    int cc = col & 1023;
                    int h = cc >> 6, d = cc & 63;
#pragma unroll
                    for (int hf = 0; hf < 2; hf++) {
                        int r = row0 + mt * 16 + hf * 8;
                        int bb = r >> 11, tt = r & 2047;
                        uint32_t p = pack2h(c[mt][nt][hf * 2], c[mt][nt][hf * 2 + 1]);
                        *(uint32_t*)&dst[((((size_t)bb * 16 + h) * 2048 + tt) << 6) + d] = p;
                    }
                }
            }
        }
    } else {
#pragma unroll
        for (int mt = 0; mt < 2; mt++) {
#pragma unroll
            for (int nt = 0; nt < 4; nt++) {
                int col = col0 + nt * 8;
#pragma unroll
                for (int hf = 0; hf < 2; hf++) {
                    int r = row0 + mt * 16 + hf * 8;
                    float2 v;
                    v.x = c[mt][nt][hf * 2 + 0];
                    v.y = c[mt][nt][hf * 2 + 1];
                    *(float2*)&out[(size_t)r * N + col] = v;
                }
            }
        }
    }
}

// ---------------------------------------------------------------------------
// Causal flash attention, register-resident softmax.
// q-tile 128, 8 warps, warp tile 16(q) x 64(k). S C-fragment == P A-fragment,
// so S/P never touch smem. One __syncthreads per kt iteration; K/V cp.async
// double-buffered, prefetched one iteration ahead. Q fragments hoisted.
// smem words: Qs[128][36]=4608, Ks[2][64][36] @4608, Vs[2][64][36] @9216.
// ---------------------------------------------------------------------------
__global__ void __launch_bounds__(256, 2) attn_reg_kernel()
{
    extern __shared__ uint32_t sm[];
    const int LDW = 36;
    uint32_t sbase = smem_u32(sm);

    int bh = blockIdx.y;
    int qt = gridDim.x - 1 - blockIdx.x;   // heavy tiles first
    int h = bh & 15, bb = bh >> 4;

    const __half* Qp = g_qh + ((size_t)bh * 2048 + qt * 128) * 64;
    const __half* Kp = g_kh + (size_t)bh * 2048 * 64;
    const __half* Vp = g_vTh + (size_t)bh * 64 * 2048;

    int tid = threadIdx.x;
    int lane = tid & 31;
    int wid = tid >> 5;        // warp owns rows 16*wid .. +15
    int g = lane >> 2;
    int t = lane & 3;

    // K/V staging chunks: 512 x 16B each, 2 per thread
    int r0 = tid >> 3,         c0 = tid & 7;
    int r1 = (tid + 256) >> 3, c1 = (tid + 256) & 7;

#define ISSUE_KV(kt_, s_)                                                     \
    {                                                                         \
        uint32_t so = (uint32_t)(s_) * 2304u * 4u;                            \
        cp16(sbase + (4608 + r0 * LDW + c0 * 4) * 4 + so,                     \
             Kp + (size_t)((kt_) * 64 + r0) * 64 + c0 * 8);                   \
        cp16(sbase + (4608 + r1 * LDW + c1 * 4) * 4 + so,                     \
             Kp + (size_t)((kt_) * 64 + r1) * 64 + c1 * 8);                   \
        cp16(sbase + (9216 + r0 * LDW + c0 * 4) * 4 + so,                     \
             Vp + (size_t)r0 * 2048 + (kt_) * 64 + c0 * 8);                   \
        cp16(sbase + (9216 + r1 * LDW + c1 * 4) * 4 + so,                     \
             Vp + (size_t)r1 * 2048 + (kt_) * 64 + c1 * 8);                   \
    }

    // prefetch K0/V0, then stage Q (plain vectorized copy)
    ISSUE_KV(0, 0);
    CP_COMMIT();
#pragma unroll
    for (int i = 0; i < 4; i++) {
        int idx = tid + i * 256;
        int qr = idx >> 3, qc = idx & 7;
        *(uint4*)&sm[qr * LDW + qc * 4] = *(const uint4*)(Qp + qr * 64 + qc * 8);
    }
    __syncthreads();

    // hoist Q fragments (16 regs)
    int a_row_l  = (lane & 7) + 8 * ((lane >> 3) & 1);
    int a_word_l = 4 * (lane >> 4);
    int b_row_l  = (lane & 7) + 8 * (lane >> 4);
    int b_word_l = 4 * ((lane >> 3) & 1);
    uint32_t aq[4][4];
#pragma unroll
    for (int ks = 0; ks < 4; ks++)
        ldsm_x4(aq[ks], sbase + ((16 * wid + a_row_l) * LDW + ks * 8 + a_word_l) * 4);

    float o[8][4];
#pragma unroll
    for (int nt = 0; nt < 8; nt++)
#pragma unroll
        for (int e = 0; e < 4; e++) o[nt][e] = 0.f;

    float m0 = -1e30f, m1 = -1e30f, l0 = 0.f, l1 = 0.f;
    const float scale = 0.125f;
    int q0g = qt * 128 + 16 * wid + g;
    int q1g = q0g + 8;
    int ktmax = 2 * qt + 1;

    for (int kt = 0; kt <= ktmax; kt++) {
        int s = kt & 1;
        CP_WAIT0();
        __syncthreads();
        if (kt < ktmax) {
            ISSUE_KV(kt + 1, s ^ 1);
            CP_COMMIT();
        }
        uint32_t kbase = sbase + (4608 + s * 2304) * 4;
        uint32_t vbase = sbase + (9216 + s * 2304) * 4;

        // S = Q K^T   (warp: 16 x 64)
        float cs[8][4];
#pragma unroll
        for (int nt = 0; nt < 8; nt++)
#pragma unroll
            for (int e = 0; e < 4; e++) cs[nt][e] = 0.f;

#pragma unroll
        for (int ks = 0; ks < 4; ks++) {
#pragma unroll
            for (int np = 0; np < 4; np++) {
                uint32_t b[4];
                ldsm_x4(b, kbase + ((np * 16 + b_row_l) * LDW + ks * 8 + b_word_l) * 4);
                mma_f16(cs[2 * np + 0], aq[ks][0], aq[ks][1], aq[ks][2], aq[ks][3],
                        b[0], b[1]);
                mma_f16(cs[2 * np + 1], aq[ks][0], aq[ks][1], aq[ks][2], aq[ks][3],
                        b[2], b[3]);
            }
        }

        // register softmax (rows g and g+8 of this warp's 16-row strip)
        int kb = kt * 64;
        float mx0 = -1e30f, mx1 = -1e30f;
#pragma unroll
        for (int nt = 0; nt < 8; nt++) {
            int j = kb + nt * 8 + 2 * t;
            cs[nt][0] = (j     <= q0g) ? cs[nt][0] * scale : -1e30f;
            cs[nt][1] = (j + 1 <= q0g) ? cs[nt][1] * scale : -1e30f;
            cs[nt][2] = (j     <= q1g) ? cs[nt][2] * scale : -1e30f;
            cs[nt][3] = (j + 1 <= q1g) ? cs[nt][3] * scale : -1e30f;
            mx0 = fmaxf(mx0, fmaxf(cs[nt][0], cs[nt][1]));
            mx1 = fmaxf(mx1, fmaxf(cs[nt][2], cs[nt][3]));
        }
        mx0 = fmaxf(mx0, __shfl_xor_sync(0xffffffffu, mx0, 1));
        mx0 = fmaxf(mx0, __shfl_xor_sync(0xffffffffu, mx0, 2));
        mx1 = fmaxf(mx1, __shfl_xor_sync(0xffffffffu, mx1, 1));
        mx1 = fmaxf(mx1, __shfl_xor_sync(0xffffffffu, mx1, 2));
        float nm0 = fmaxf(m0, mx0), nm1 = fmaxf(m1, mx1);
        float corr0 = __expf(m0 - nm0), corr1 = __expf(m1 - nm1);
        m0 = nm0; m1 = nm1;
        float s0 = 0.f, s1 = 0.f;
#pragma unroll
        for (int nt = 0; nt < 8; nt++) {
            cs[nt][0] = __expf(cs[nt][0] - nm0); s0 += cs[nt][0];
            cs[nt][1] = __expf(cs[nt][1] - nm0); s0 += cs[nt][1];
            cs[nt][2] = __expf(cs[nt][2] - nm1); s1 += cs[nt][2];
            cs[nt][3] = __expf(cs[nt][3] - nm1); s1 += cs[nt][3];
        }
        s0 += __shfl_xor_sync(0xffffffffu, s0, 1);
        s0 += __shfl_xor_sync(0xffffffffu, s0, 2);
        s1 += __shfl_xor_sync(0xffffffffu, s1, 1);
        s1 += __shfl_xor_sync(0xffffffffu, s1, 2);
        l0 = l0 * corr0 + s0;
        l1 = l1 * corr1 + s1;
#pragma unroll
        for (int nt = 0; nt < 8; nt++) {
            o[nt][0] *= corr0; o[nt][1] *= corr0;
            o[nt][2] *= corr1; o[nt][3] *= corr1;
        }

        // O += P V   (P A-fragment == packed S C-fragment)
#pragma unroll
        for (int ks = 0; ks < 4; ks++) {
            uint32_t a0 = pack2h(cs[2 * ks][0],     cs[2 * ks][1]);
            uint32_t a1 = pack2h(cs[2 * ks][2],     cs[2 * ks][3]);
            uint32_t a2 = pack2h(cs[2 * ks + 1][0], cs[2 * ks + 1][1]);
            uint32_t a3 = pack2h(cs[2 * ks + 1][2], cs[2 * ks + 1][3]);
#pragma unroll
            for (int np = 0; np < 4; np++) {
                uint32_t b[4];
                ldsm_x4(b, vbase + ((np * 16 + b_row_l) * LDW + ks * 8 + b_word_l) * 4);
                mma_f16(o[2 * np + 0], a0, a1, a2, a3, b[0], b[1]);
                mma_f16(o[2 * np + 1], a0, a1, a2, a3, b[2], b[3]);
            }
        }
    }
#undef ISSUE_KV

    // epilogue: normalize, write ctx fp16 [B,T,C]
    float il0 = 1.f / l0, il1 = 1.f / l1;
#pragma unroll
    for (int nt = 0; nt < 8; nt++) {
        int d = nt * 8 + 2 * t;
        *(uint32_t*)&g_ctxh[((size_t)bb * 2048 + q0g) * 1024 + h * 64 + d] =
            pack2h(o[nt][0] * il0, o[nt][1] * il0);
        *(uint32_t*)&g_ctxh[((size_t)bb * 2048 + q1g) * 1024 + h * 64 + d] =
            pack2h(o[nt][2] * il1, o[nt][3] * il1);
    }
}

// ---------------------------------------------------------------------------
extern "C" void kernel_launch(void* const* d_in, const int* in_sizes, int n_in,
                              void* d_out, int out_size)
{
    const float* x     = (const float*)d_in[0];  // [4,2048,1024]
    const float* w_qkv = (const float*)d_in[1];  // [1024,3072]
    const float* w_out = (const float*)d_in[2];  // [1024,1024]
    float* out = (float*)d_out;                  // [4,2048,1024]

    (void)in_sizes; (void)n_in; (void)out_size;

    const int gemm_smem = 3 * 2 * 128 * 36 * 4;   // 110592
    const int attn_smem = 13824 * 4;              // 55296

    cudaFuncSetAttribute(hgemm<0>,
                         cudaFuncAttributeMaxDynamicSharedMemorySize, gemm_smem);
    cudaFuncSetAttribute(hgemm<1>,
                         cudaFuncAttributeMaxDynamicSharedMemorySize, gemm_smem);
    cudaFuncSetAttribute(attn_reg_kernel,
                         cudaFuncAttributeMaxDynamicSharedMemorySize, attn_smem);

    // 0) conversions: x -> fp16; weights -> transposed fp16
    conv_x_kernel<<<QKV_ELEMS / 4 / 256, 256>>>(x);
    convT_kernel<3072><<<dim3(96, 32), 256>>>(w_qkv, 0);
    convT_kernel<1024><<<dim3(32, 32), 256>>>(w_out, 1);

    // 1) QKV projection: M=8192, N=3072 (v written transposed)
    hgemm<0><<<dim3(24, 64), 512, gemm_smem>>>(nullptr);

    // 2) causal flash attention (register softmax, q-tile 128)
    attn_reg_kernel<<<dim3(16, 64), 256, attn_smem>>>();

    // 3) output projection: M=8192, N=1024
    hgemm<1><<<dim3(8, 64), 512, gemm_smem>>>(out);
}